// round 6
// baseline (speedup 1.0000x reference)
#include <cuda_runtime.h>
#include <math.h>

// Problem constants
#define T_STEPS 1024
#define D_IN    2048
#define NH      2048
#define CATS    1000

// Recurrence kernel config
#define NBLK    128          // persistent blocks (1 block/SM)
#define NTH     1024         // 32 warps
#define HPB     16           // hidden indices owned per block (z AND ht)
#define NSTAGE  27           // rows of U pinned in SMEM per block (of 32)
// smem: U rows + p (block-local) + 4x32 partials
#define SMEM_FLOATS (NSTAGE*NH + NH + 128)
#define SMEM_BYTES  (SMEM_FLOATS * 4)

// Scratch (device globals; no allocation allowed)
__device__ float g_XZ[T_STEPS * NH];
__device__ float g_XH[T_STEPS * NH];
__device__ float g_Zb[4][NH];      // gate z, 4-deep ring by generation&3
__device__ float g_HTb[4][NH];     // gate htilde
__device__ float g_LOGITS[1024];
// Broadcast-flag barrier: single arrival counter + per-block flag lines
// (128B apart). Flags monotonic across launches; counter self-resets.
__device__ unsigned int g_cnt;
__device__ unsigned int g_flag[NBLK * 32];

// ---------------------------------------------------------------------------
// GEMM: C[t, n] = sum_k x[t,k] * W[n,k]; n<2048 -> Wz -> XZ, else Wh -> XH.
// ---------------------------------------------------------------------------
#define GBM 128
#define GBN 64
#define GBK 16

__global__ __launch_bounds__(256) void gemm_xproj(
    const float* __restrict__ x,
    const float* __restrict__ Wz,
    const float* __restrict__ Wh)
{
    __shared__ float As[GBK][GBM + 2];
    __shared__ float Bs[GBK][GBN + 2];

    const int tid  = threadIdx.x;
    const int row0 = blockIdx.y * GBM;
    const int col0 = blockIdx.x * GBN;

    const float* Bbase = (col0 < NH) ? (Wz + (size_t)col0 * D_IN)
                                     : (Wh + (size_t)(col0 - NH) * D_IN);

    const int trow = tid >> 4;
    const int tcol = tid & 15;
    const int m0 = trow * 8;
    const int n0 = tcol * 4;

    float acc[8][4];
    #pragma unroll
    for (int i = 0; i < 8; i++)
        #pragma unroll
        for (int j = 0; j < 4; j++) acc[i][j] = 0.f;

    for (int kt = 0; kt < D_IN; kt += GBK) {
        #pragma unroll
        for (int u = 0; u < 2; u++) {
            int idx = tid + u * 256;
            int ar  = idx >> 2;
            int ac4 = idx & 3;
            float4 v = *(const float4*)(x + (size_t)(row0 + ar) * D_IN + kt + ac4 * 4);
            As[ac4 * 4 + 0][ar] = v.x;
            As[ac4 * 4 + 1][ar] = v.y;
            As[ac4 * 4 + 2][ar] = v.z;
            As[ac4 * 4 + 3][ar] = v.w;
        }
        {
            int br  = tid >> 2;
            int bc4 = tid & 3;
            float4 v = *(const float4*)(Bbase + (size_t)br * D_IN + kt + bc4 * 4);
            Bs[bc4 * 4 + 0][br] = v.x;
            Bs[bc4 * 4 + 1][br] = v.y;
            Bs[bc4 * 4 + 2][br] = v.z;
            Bs[bc4 * 4 + 3][br] = v.w;
        }
        __syncthreads();

        #pragma unroll
        for (int k = 0; k < GBK; k++) {
            float a[8], bb[4];
            #pragma unroll
            for (int i = 0; i < 8; i++) a[i] = As[k][m0 + i];
            #pragma unroll
            for (int j = 0; j < 4; j++) bb[j] = Bs[k][n0 + j];
            #pragma unroll
            for (int i = 0; i < 8; i++)
                #pragma unroll
                for (int j = 0; j < 4; j++) acc[i][j] += a[i] * bb[j];
        }
        __syncthreads();
    }

    #pragma unroll
    for (int i = 0; i < 8; i++) {
        int t = row0 + m0 + i;
        #pragma unroll
        for (int j = 0; j < 4; j++) {
            int n = col0 + n0 + j;
            if (n < NH) g_XZ[(size_t)t * NH + n] = acc[i][j];
            else        g_XH[(size_t)t * NH + (n - NH)] = acc[i][j];
        }
    }
}

// ---------------------------------------------------------------------------
// Broadcast-flag grid barrier. Arrive: one acq_rel atomic on g_cnt. Last
// arriver's warp fans the target generation out to all 128 per-block flag
// lines; every other block polls ONLY its own line (no poll contention).
// ---------------------------------------------------------------------------
__device__ __forceinline__ void grid_sync(int b, unsigned int target)
{
    __syncthreads();
    if (threadIdx.x < 32) {
        unsigned int old = 0;
        if (threadIdx.x == 0)
            asm volatile("atom.acq_rel.gpu.global.add.u32 %0, [%1], 1;"
                         : "=r"(old) : "l"(&g_cnt));
        old = __shfl_sync(0xffffffffu, old, 0);
        if (old == NBLK - 1) {
            if (threadIdx.x == 0)
                asm volatile("st.relaxed.gpu.global.u32 [%0], %1;"
                             :: "l"(&g_cnt), "r"(0u));
            #pragma unroll
            for (int i = threadIdx.x; i < NBLK; i += 32)
                asm volatile("st.release.gpu.global.u32 [%0], %1;"
                             :: "l"(&g_flag[i * 32]), "r"(target));
        } else if (threadIdx.x == 0) {
            unsigned int v;
            do {
                asm volatile("ld.acquire.gpu.global.u32 %0, [%1];"
                             : "=r"(v) : "l"(&g_flag[b * 32]));
            } while ((int)(v - target) < 0);
        }
    }
    __syncthreads();
}

// ---------------------------------------------------------------------------
// Persistent recurrence. Block b owns hidden indices [16b,16b+16).
// p is BLOCK-LOCAL smem, rolled redundantly by every block; only gates are
// exchanged. Two timesteps per superstep, ONE grid barrier per superstep.
// Matvec: 4-way K split (warp kq = w>>3 handles K quarter), warp wp = w&7
// handles rows wp, wp+8 (z) and wp+16, wp+24 (ht).
// ---------------------------------------------------------------------------
__global__ __launch_bounds__(NTH, 1) void gru_recurrence(
    const float* __restrict__ Uz, const float* __restrict__ Uh,
    const float* __restrict__ bz,
    const float* __restrict__ Wout,
    const float* __restrict__ zt0, const float* __restrict__ htilde0,
    const float* __restrict__ hprev0,
    float* __restrict__ out)
{
    extern __shared__ float sm[];
    float* smU  = sm;                   // NSTAGE * NH
    float* ps   = sm + NSTAGE * NH;     // NH : persistent local copy of p
    float* part = ps + NH;              // 4 x 32 partials [kq*32 + row]

    const int tid  = threadIdx.x;
    const int w    = tid >> 5;
    const int lane = tid & 31;
    const int wp   = w & 7;             // row group
    const int kq   = w >> 3;            // K quarter (0..3)
    const int b    = blockIdx.x;
    const int I0   = b * HPB;

    // Launch-start flag base (all flags equal between launches).
    unsigned int base = 0;
    if (w == 0)
        asm volatile("ld.relaxed.gpu.global.u32 %0, [%1];"
                     : "=r"(base) : "l"(&g_flag[b * 32]));

    // Pin NSTAGE matvec rows into SMEM. Row s: s<16 -> Uz[I0+s], else Uh[I0+s-16].
    for (int s = 0; s < NSTAGE; s++) {
        const float* src = (s < 16) ? (Uz + (size_t)(I0 + s) * NH)
                                    : (Uh + (size_t)(I0 + s - 16) * NH);
        for (int i = tid; i < NH / 4; i += NTH)
            ((float4*)(smU + (size_t)s * NH))[i] = ((const float4*)src)[i];
    }
    // p_0 = hprev0 (block-local full copy); only tid<512 carry p elements
    float4* ps4 = (float4*)ps;
    if (tid < NH / 4) ps4[tid] = ((const float4*)hprev0)[tid];

    const float bzv = (tid < 16) ? __ldg(bz + I0 + tid) : 0.f;

    // Per-warp row pointers (K-quarter slices, float4 indexed j*32+lane, j<4)
    const int s3 = wp + 24;                       // only it=3 can be residual
    const bool resid = (s3 >= NSTAGE);
    const float4* r0 = (const float4*)(smU + (size_t)(wp)      * NH + kq * 512);
    const float4* r1 = (const float4*)(smU + (size_t)(wp + 8)  * NH + kq * 512);
    const float4* r2 = (const float4*)(smU + (size_t)(wp + 16) * NH + kq * 512);
    const float4* r3 = resid
        ? (const float4*)(Uh + (size_t)(I0 + s3 - 16) * NH + kq * 512)
        : (const float4*)(smU + (size_t)s3 * NH + kq * 512);

    __syncthreads();

    // ---- matvec over current smem p, producing gate generation -> buf ----
    auto matvec_gates = [&](int buf, float xv) {
        float4 preg[4];
        #pragma unroll
        for (int j = 0; j < 4; j++) preg[j] = ps4[kq * 128 + j * 32 + lane];

        float a0 = 0.f, a1 = 0.f, a2 = 0.f, a3 = 0.f;
        #pragma unroll
        for (int j = 0; j < 4; j++) {
            float4 p = preg[j];
            float4 u;
            u = r0[j * 32 + lane];
            a0 += u.x * p.x + u.y * p.y + u.z * p.z + u.w * p.w;
            u = r1[j * 32 + lane];
            a1 += u.x * p.x + u.y * p.y + u.z * p.z + u.w * p.w;
            u = r2[j * 32 + lane];
            a2 += u.x * p.x + u.y * p.y + u.z * p.z + u.w * p.w;
            u = resid ? __ldg(r3 + j * 32 + lane) : r3[j * 32 + lane];
            a3 += u.x * p.x + u.y * p.y + u.z * p.z + u.w * p.w;
        }
        #pragma unroll
        for (int off = 16; off; off >>= 1) {
            a0 += __shfl_xor_sync(0xffffffffu, a0, off);
            a1 += __shfl_xor_sync(0xffffffffu, a1, off);
            a2 += __shfl_xor_sync(0xffffffffu, a2, off);
            a3 += __shfl_xor_sync(0xffffffffu, a3, off);
        }
        if (lane == 0) {
            float* pt = part + kq * 32;
            pt[wp]      = a0;
            pt[wp + 8]  = a1;
            pt[wp + 16] = a2;
            pt[wp + 24] = a3;
        }
        __syncthreads();
        if (tid < 32) {
            float v = part[tid] + part[32 + tid] + part[64 + tid] + part[96 + tid];
            if (tid < 16) {
                float pre = xv + v + bzv;
                g_Zb[buf][I0 + tid] = 1.f / (1.f + expf(-pre));
            } else {
                g_HTb[buf][I0 + tid - 16] = tanhf(xv + v);
            }
        }
    };

    // ---- supersteps: 2 timesteps, ONE grid barrier each ----
    for (int m = 0; m < T_STEPS / 2; m++) {
        const int t = 2 * m;

        // Prefetch gates for roll A (gen t-1) and roll B (gen t) up front.
        float4 zA, hA, zB, hB;
        if (tid < NH / 4) {
            if (m > 0) {
                const int bA = (t - 1) & 3;
                zA = __ldcg((const float4*)g_Zb[bA]  + tid);
                hA = __ldcg((const float4*)g_HTb[bA] + tid);
                const int bB = t & 3;
                zB = __ldcg((const float4*)g_Zb[bB]  + tid);
                hB = __ldcg((const float4*)g_HTb[bB] + tid);
            } else {
                zB = ((const float4*)zt0)[tid];
                hB = ((const float4*)htilde0)[tid];
            }
        }
        // x projections for both matvecs (gate warp only)
        float xv0 = 0.f, xv1 = 0.f;
        if (tid < 32) {
            if (tid < 16) {
                xv0 = __ldg(&g_XZ[(size_t)t * NH + I0 + tid]);
                xv1 = __ldg(&g_XZ[(size_t)(t + 1) * NH + I0 + tid]);
            } else {
                xv0 = __ldg(&g_XH[(size_t)t * NH + I0 + tid - 16]);
                xv1 = __ldg(&g_XH[(size_t)(t + 1) * NH + I0 + tid - 16]);
            }
        }

        // Roll A: p_t = (1-z_{t-1})*p_{t-1} + z_{t-1}*ht_{t-1}  (skip at m=0)
        if (m > 0) {
            if (tid < NH / 4) {
                float4 p = ps4[tid];
                p.x = (1.f - zA.x) * p.x + zA.x * hA.x;
                p.y = (1.f - zA.y) * p.y + zA.y * hA.y;
                p.z = (1.f - zA.z) * p.z + zA.z * hA.z;
                p.w = (1.f - zA.w) * p.w + zA.w * hA.w;
                ps4[tid] = p;
            }
            __syncthreads();
        }

        // Matvec over p_t -> gates G(2m+1)
        matvec_gates((t + 1) & 3, xv0);
        __syncthreads();

        // Roll B: p_{t+1} = (1-z_t)*p_t + z_t*ht_t
        if (tid < NH / 4) {
            float4 p = ps4[tid];
            p.x = (1.f - zB.x) * p.x + zB.x * hB.x;
            p.y = (1.f - zB.y) * p.y + zB.y * hB.y;
            p.z = (1.f - zB.z) * p.z + zB.z * hB.z;
            p.w = (1.f - zB.w) * p.w + zB.w * hB.w;
            ps4[tid] = p;
        }
        __syncthreads();

        // Matvec over p_{t+1} -> gates G(2m+2)
        matvec_gates((t + 2) & 3, xv1);

        grid_sync(b, base + m + 1);   // all gate stores visible chip-wide
    }

    // Final roll: p_1024 = (1-z_1023)*p_1023 + z_1023*ht_1023
    if (tid < NH / 4) {
        const int bF = (T_STEPS - 1) & 3;
        float4 z = __ldcg((const float4*)g_Zb[bF]  + tid);
        float4 h = __ldcg((const float4*)g_HTb[bF] + tid);
        float4 p = ps4[tid];
        p.x = (1.f - z.x) * p.x + z.x * h.x;
        p.y = (1.f - z.y) * p.y + z.y * h.y;
        p.z = (1.f - z.z) * p.z + z.z * h.z;
        p.w = (1.f - z.w) * p.w + z.w * h.w;
        ps4[tid] = p;
    }
    __syncthreads();

    // Logits: warp gw = b*32 + w covers 1000 rows (p from local smem)
    {
        int gw = b * 32 + w;
        if (gw < CATS) {
            const float4* u4 = (const float4*)(Wout + (size_t)gw * NH);
            float acc = 0.f;
            #pragma unroll
            for (int j = 0; j < 16; j++) {
                float4 u = __ldg(u4 + j * 32 + lane);
                float4 p = ps4[j * 32 + lane];
                acc += u.x * p.x + u.y * p.y + u.z * p.z + u.w * p.w;
            }
            #pragma unroll
            for (int off = 16; off; off >>= 1)
                acc += __shfl_xor_sync(0xffffffffu, acc, off);
            if (lane == 0) g_LOGITS[gw] = acc;
        }
    }
    grid_sync(b, base + T_STEPS / 2 + 1);

    // Softmax in block 0 (reduction buffer reuses ps)
    if (b == 0) {
        float* red = ps;
        float lm = -1e30f;
        for (int c = tid; c < CATS; c += NTH) lm = fmaxf(lm, __ldcg(&g_LOGITS[c]));
        __syncthreads();
        red[tid] = lm; __syncthreads();
        for (int o = NTH / 2; o; o >>= 1) {
            if (tid < o) red[tid] = fmaxf(red[tid], red[tid + o]);
            __syncthreads();
        }
        float mx = red[0]; __syncthreads();
        float ls = 0.f;
        for (int c = tid; c < CATS; c += NTH) ls += expf(__ldcg(&g_LOGITS[c]) - mx);
        red[tid] = ls; __syncthreads();
        for (int o = NTH / 2; o; o >>= 1) {
            if (tid < o) red[tid] += red[tid + o];
            __syncthreads();
        }
        float inv = 1.f / red[0];
        for (int c = tid; c < CATS; c += NTH)
            out[c] = expf(__ldcg(&g_LOGITS[c]) - mx) * inv;
    }
}

// ---------------------------------------------------------------------------
extern "C" void kernel_launch(void* const* d_in, const int* in_sizes, int n_in,
                              void* d_out, int out_size)
{
    const float* x       = (const float*)d_in[0];
    const float* Wh      = (const float*)d_in[1];
    const float* Wz      = (const float*)d_in[2];
    // d_in[3] = Wr, d_in[7] = Ur, d_in[8] = br: dead code in reference
    const float* Uh      = (const float*)d_in[4];
    const float* Uz      = (const float*)d_in[5];
    const float* bz      = (const float*)d_in[6];
    const float* Wout    = (const float*)d_in[9];
    // d_in[10] = h0: never read by the reference recurrence
    const float* zt0     = (const float*)d_in[11];
    const float* htilde0 = (const float*)d_in[12];
    const float* hprev0  = (const float*)d_in[13];
    float* out = (float*)d_out;

    dim3 ggrid((NH * 2) / GBN, T_STEPS / GBM);
    gemm_xproj<<<ggrid, 256>>>(x, Wz, Wh);

    cudaFuncSetAttribute(gru_recurrence,
                         cudaFuncAttributeMaxDynamicSharedMemorySize, SMEM_BYTES);
    gru_recurrence<<<NBLK, NTH, SMEM_BYTES>>>(Uz, Uh, bz, Wout,
                                              zt0, htilde0, hprev0, out);
}

// round 11
// speedup vs baseline: 1.5730x; 1.5730x over previous
#include <cuda_runtime.h>
#include <math.h>

// Problem constants
#define T_STEPS 1024
#define D_IN    2048
#define NH      2048
#define CATS    1000

// Recurrence kernel config
#define NBLK    128          // persistent blocks (1 block/SM)
#define NTH     512          // 16 warps
#define HPB     16           // hidden indices owned per block (z AND ht)
#define NSTAGE  26           // rows of U pinned in SMEM per block (of 32)
// smem: U rows + two p buffers (p_t, p_{t+1}) + 128 partials
#define SMEM_FLOATS (NSTAGE*NH + 2*NH + 128)
#define SMEM_BYTES  (SMEM_FLOATS * 4)   // 229888 B

// Scratch (device globals; no allocation allowed)
__device__ float g_XZ[T_STEPS * NH];
__device__ float g_XH[T_STEPS * NH];
__device__ float g_Zb[4][NH];      // gate z, 4-deep ring by generation&3
__device__ float g_HTb[4][NH];     // gate htilde
__device__ float g_LOGITS[1024];
// Barrier state on separate 256B lines (pollers never touch the count line)
__device__ unsigned int g_count[64];
__device__ unsigned int g_gen[64];

// ---------------------------------------------------------------------------
// GEMM: C[t, n] = sum_k x[t,k] * W[n,k]; n<2048 -> Wz -> XZ, else Wh -> XH.
// ---------------------------------------------------------------------------
#define GBM 128
#define GBN 64
#define GBK 16

__global__ __launch_bounds__(256) void gemm_xproj(
    const float* __restrict__ x,
    const float* __restrict__ Wz,
    const float* __restrict__ Wh)
{
    __shared__ float As[GBK][GBM + 2];
    __shared__ float Bs[GBK][GBN + 2];

    const int tid  = threadIdx.x;
    const int row0 = blockIdx.y * GBM;
    const int col0 = blockIdx.x * GBN;

    const float* Bbase = (col0 < NH) ? (Wz + (size_t)col0 * D_IN)
                                     : (Wh + (size_t)(col0 - NH) * D_IN);

    const int trow = tid >> 4;
    const int tcol = tid & 15;
    const int m0 = trow * 8;
    const int n0 = tcol * 4;

    float acc[8][4];
    #pragma unroll
    for (int i = 0; i < 8; i++)
        #pragma unroll
        for (int j = 0; j < 4; j++) acc[i][j] = 0.f;

    for (int kt = 0; kt < D_IN; kt += GBK) {
        #pragma unroll
        for (int u = 0; u < 2; u++) {
            int idx = tid + u * 256;
            int ar  = idx >> 2;
            int ac4 = idx & 3;
            float4 v = *(const float4*)(x + (size_t)(row0 + ar) * D_IN + kt + ac4 * 4);
            As[ac4 * 4 + 0][ar] = v.x;
            As[ac4 * 4 + 1][ar] = v.y;
            As[ac4 * 4 + 2][ar] = v.z;
            As[ac4 * 4 + 3][ar] = v.w;
        }
        {
            int br  = tid >> 2;
            int bc4 = tid & 3;
            float4 v = *(const float4*)(Bbase + (size_t)br * D_IN + kt + bc4 * 4);
            Bs[bc4 * 4 + 0][br] = v.x;
            Bs[bc4 * 4 + 1][br] = v.y;
            Bs[bc4 * 4 + 2][br] = v.z;
            Bs[bc4 * 4 + 3][br] = v.w;
        }
        __syncthreads();

        #pragma unroll
        for (int k = 0; k < GBK; k++) {
            float a[8], bb[4];
            #pragma unroll
            for (int i = 0; i < 8; i++) a[i] = As[k][m0 + i];
            #pragma unroll
            for (int j = 0; j < 4; j++) bb[j] = Bs[k][n0 + j];
            #pragma unroll
            for (int i = 0; i < 8; i++)
                #pragma unroll
                for (int j = 0; j < 4; j++) acc[i][j] += a[i] * bb[j];
        }
        __syncthreads();
    }

    #pragma unroll
    for (int i = 0; i < 8; i++) {
        int t = row0 + m0 + i;
        #pragma unroll
        for (int j = 0; j < 4; j++) {
            int n = col0 + n0 + j;
            if (n < NH) g_XZ[(size_t)t * NH + n] = acc[i][j];
            else        g_XH[(size_t)t * NH + (n - NH)] = acc[i][j];
        }
    }
}

// ---------------------------------------------------------------------------
// Single-counter atomic + generation-broadcast barrier (round-4 proven),
// with count and gen on separate L2 lines.
// ---------------------------------------------------------------------------
__device__ __forceinline__ void grid_sync()
{
    __syncthreads();
    if (threadIdx.x == 0) {
        unsigned int gen;
        asm volatile("ld.acquire.gpu.global.u32 %0, [%1];"
                     : "=r"(gen) : "l"(&g_gen[0]));
        unsigned int old;
        asm volatile("atom.release.gpu.global.add.u32 %0, [%1], 1;"
                     : "=r"(old) : "l"(&g_count[0]));
        if (old == NBLK - 1) {
            asm volatile("st.relaxed.gpu.global.u32 [%0], %1;"
                         :: "l"(&g_count[0]), "r"(0u));
            asm volatile("st.release.gpu.global.u32 [%0], %1;"
                         :: "l"(&g_gen[0]), "r"(gen + 1u));
        } else {
            unsigned int v;
            do {
                asm volatile("ld.acquire.gpu.global.u32 %0, [%1];"
                             : "=r"(v) : "l"(&g_gen[0]));
            } while (v == gen);
        }
    }
    __syncthreads();
}

// ---------------------------------------------------------------------------
// Persistent recurrence. Block b owns hidden indices [16b,16b+16).
// FUSED superstep: after the barrier, gates G(2m-1), G(2m) are both known,
// so p_t AND p_{t+1} are both computable immediately. One pass over U
// computes BOTH matvecs (each staged U element read once, FMA'd against
// p_t and p_{t+1}), producing G(2m+1), G(2m+2). One barrier per superstep.
// Warp (wp = w&7, kh = w>>3): rows wp, wp+8 (z), wp+16, wp+24 (ht), K-half kh.
// ---------------------------------------------------------------------------
__global__ __launch_bounds__(NTH, 1) void gru_recurrence(
    const float* __restrict__ Uz, const float* __restrict__ Uh,
    const float* __restrict__ bz,
    const float* __restrict__ Wout,
    const float* __restrict__ zt0, const float* __restrict__ htilde0,
    const float* __restrict__ hprev0,
    float* __restrict__ out)
{
    extern __shared__ float sm[];
    float* smU  = sm;                    // NSTAGE * NH
    float* psA  = sm + NSTAGE * NH;      // NH : p_t
    float* psB  = psA + NH;              // NH : p_{t+1}
    float* part = psB + NH;              // 128 partials [vec*64 + kh*32 + row]

    const int tid  = threadIdx.x;
    const int w    = tid >> 5;
    const int lane = tid & 31;
    const int wp   = w & 7;              // row group
    const int kh   = w >> 3;             // K half
    const int b    = blockIdx.x;
    const int I0   = b * HPB;

    // Pin NSTAGE matvec rows into SMEM. Row s: s<16 -> Uz[I0+s], else Uh[I0+s-16].
    for (int s = 0; s < NSTAGE; s++) {
        const float* src = (s < 16) ? (Uz + (size_t)(I0 + s) * NH)
                                    : (Uh + (size_t)(I0 + s - 16) * NH);
        for (int i = tid; i < NH / 4; i += NTH)
            ((float4*)(smU + (size_t)s * NH))[i] = ((const float4*)src)[i];
    }

    float4* psA4 = (float4*)psA;
    float4* psB4 = (float4*)psB;

    const float bzv = (tid < 16) ? __ldg(bz + I0 + tid) : 0.f;

    // Per-warp row pointers (K-half slices; float4 index j*32+lane, j<8)
    const int s3 = wp + 24;                       // only it=3 can be residual
    const bool resid = (s3 >= NSTAGE);
    const float4* r0 = (const float4*)(smU + (size_t)(wp)      * NH + kh * 1024);
    const float4* r1 = (const float4*)(smU + (size_t)(wp + 8)  * NH + kh * 1024);
    const float4* r2 = (const float4*)(smU + (size_t)(wp + 16) * NH + kh * 1024);
    const float4* r3 = resid
        ? (const float4*)(Uh + (size_t)(I0 + s3 - 16) * NH + kh * 1024)
        : (const float4*)(smU + (size_t)s3 * NH + kh * 1024);

    __syncthreads();

    // ---- supersteps: 2 timesteps, 1 fused U pass, 1 grid barrier ----
    for (int m = 0; m < T_STEPS / 2; m++) {
        const int t = 2 * m;

        // Prefetch gates for both rolls (G(2m-1), G(2m)) right after barrier.
        float4 zA, hA, zB, hB;
        if (m > 0) {
            const int bA = (t - 1) & 3;
            zA = __ldcg((const float4*)g_Zb[bA]  + tid);
            hA = __ldcg((const float4*)g_HTb[bA] + tid);
            const int bB = t & 3;
            zB = __ldcg((const float4*)g_Zb[bB]  + tid);
            hB = __ldcg((const float4*)g_HTb[bB] + tid);
        } else {
            zB = ((const float4*)zt0)[tid];
            hB = ((const float4*)htilde0)[tid];
        }
        // Residual U row prefetch (constant data; hides L2 latency)
        float4 upre[8];
        if (resid) {
            #pragma unroll
            for (int j = 0; j < 8; j++) upre[j] = __ldg(r3 + j * 32 + lane);
        }
        // x projections for both steps (gate warp only)
        float xv0 = 0.f, xv1 = 0.f;
        if (tid < 32) {
            if (tid < 16) {
                xv0 = __ldg(&g_XZ[(size_t)t * NH + I0 + tid]);
                xv1 = __ldg(&g_XZ[(size_t)(t + 1) * NH + I0 + tid]);
            } else {
                xv0 = __ldg(&g_XH[(size_t)t * NH + I0 + tid - 16]);
                xv1 = __ldg(&g_XH[(size_t)(t + 1) * NH + I0 + tid - 16]);
            }
        }

        // Both rolls, back to back (each thread owns element tid):
        // p_t = roll(p_{t-1}, G(2m-1));  p_{t+1} = roll(p_t, G(2m))
        {
            float4 p = (m == 0) ? ((const float4*)hprev0)[tid] : psB4[tid];
            if (m > 0) {
                p.x = (1.f - zA.x) * p.x + zA.x * hA.x;
                p.y = (1.f - zA.y) * p.y + zA.y * hA.y;
                p.z = (1.f - zA.z) * p.z + zA.z * hA.z;
                p.w = (1.f - zA.w) * p.w + zA.w * hA.w;
            }
            psA4[tid] = p;
            float4 q;
            q.x = (1.f - zB.x) * p.x + zB.x * hB.x;
            q.y = (1.f - zB.y) * p.y + zB.y * hB.y;
            q.z = (1.f - zB.z) * p.z + zB.z * hB.z;
            q.w = (1.f - zB.w) * p.w + zB.w * hB.w;
            psB4[tid] = q;
        }
        __syncthreads();

        // Fused dual matvec: one pass over U, FMA vs p_t AND p_{t+1}
        float aA0 = 0.f, aA1 = 0.f, aA2 = 0.f, aA3 = 0.f;
        float aB0 = 0.f, aB1 = 0.f, aB2 = 0.f, aB3 = 0.f;
        #pragma unroll
        for (int j = 0; j < 8; j++) {
            float4 pA = psA4[kh * 256 + j * 32 + lane];
            float4 pB = psB4[kh * 256 + j * 32 + lane];
            float4 u;
            u = r0[j * 32 + lane];
            aA0 += u.x * pA.x + u.y * pA.y + u.z * pA.z + u.w * pA.w;
            aB0 += u.x * pB.x + u.y * pB.y + u.z * pB.z + u.w * pB.w;
            u = r1[j * 32 + lane];
            aA1 += u.x * pA.x + u.y * pA.y + u.z * pA.z + u.w * pA.w;
            aB1 += u.x * pB.x + u.y * pB.y + u.z * pB.z + u.w * pB.w;
            u = r2[j * 32 + lane];
            aA2 += u.x * pA.x + u.y * pA.y + u.z * pA.z + u.w * pA.w;
            aB2 += u.x * pB.x + u.y * pB.y + u.z * pB.z + u.w * pB.w;
            u = resid ? upre[j] : r3[j * 32 + lane];
            aA3 += u.x * pA.x + u.y * pA.y + u.z * pA.z + u.w * pA.w;
            aB3 += u.x * pB.x + u.y * pB.y + u.z * pB.z + u.w * pB.w;
        }
        #pragma unroll
        for (int off = 16; off; off >>= 1) {
            aA0 += __shfl_xor_sync(0xffffffffu, aA0, off);
            aA1 += __shfl_xor_sync(0xffffffffu, aA1, off);
            aA2 += __shfl_xor_sync(0xffffffffu, aA2, off);
            aA3 += __shfl_xor_sync(0xffffffffu, aA3, off);
            aB0 += __shfl_xor_sync(0xffffffffu, aB0, off);
            aB1 += __shfl_xor_sync(0xffffffffu, aB1, off);
            aB2 += __shfl_xor_sync(0xffffffffu, aB2, off);
            aB3 += __shfl_xor_sync(0xffffffffu, aB3, off);
        }
        if (lane == 0) {
            float* pa = part + kh * 32;        // vec A partials
            pa[wp]      = aA0;
            pa[wp + 8]  = aA1;
            pa[wp + 16] = aA2;
            pa[wp + 24] = aA3;
            float* pb = part + 64 + kh * 32;   // vec B partials
            pb[wp]      = aB0;
            pb[wp + 8]  = aB1;
            pb[wp + 16] = aB2;
            pb[wp + 24] = aB3;
        }
        __syncthreads();

        // Gate warp: both generations at once
        if (tid < 32) {
            float vA = part[tid]      + part[32 + tid];
            float vB = part[64 + tid] + part[96 + tid];
            const int gA = (t + 1) & 3, gB = (t + 2) & 3;
            if (tid < 16) {
                g_Zb[gA][I0 + tid] = 1.f / (1.f + expf(-(xv0 + vA + bzv)));
                g_Zb[gB][I0 + tid] = 1.f / (1.f + expf(-(xv1 + vB + bzv)));
            } else {
                g_HTb[gA][I0 + tid - 16] = tanhf(xv0 + vA);
                g_HTb[gB][I0 + tid - 16] = tanhf(xv1 + vB);
            }
        }

        grid_sync();   // all gate stores visible chip-wide
    }

    // Final roll: p_1024 = roll(p_1023, G(1023)); result into psA
    {
        const int bF = (T_STEPS - 1) & 3;
        float4 z = __ldcg((const float4*)g_Zb[bF]  + tid);
        float4 h = __ldcg((const float4*)g_HTb[bF] + tid);
        float4 p = psB4[tid];
        p.x = (1.f - z.x) * p.x + z.x * h.x;
        p.y = (1.f - z.y) * p.y + z.y * h.y;
        p.z = (1.f - z.z) * p.z + z.z * h.z;
        p.w = (1.f - z.w) * p.w + z.w * h.w;
        psA4[tid] = p;
    }
    __syncthreads();

    // Logits: warp gw = b*16 + w covers 1000 rows (p from local smem)
    {
        int gw = b * 16 + w;
        if (gw < CATS) {
            const float4* u4 = (const float4*)(Wout + (size_t)gw * NH);
            float acc = 0.f;
            #pragma unroll
            for (int j = 0; j < 16; j++) {
                float4 u = __ldg(u4 + j * 32 + lane);
                float4 p = psA4[j * 32 + lane];
                acc += u.x * p.x + u.y * p.y + u.z * p.z + u.w * p.w;
            }
            #pragma unroll
            for (int off = 16; off; off >>= 1)
                acc += __shfl_xor_sync(0xffffffffu, acc, off);
            if (lane == 0) g_LOGITS[gw] = acc;
        }
    }
    grid_sync();

    // Softmax in block 0 (reduction buffer reuses psB)
    if (b == 0) {
        float* red = psB;
        float lm = -1e30f;
        for (int c = tid; c < CATS; c += NTH) lm = fmaxf(lm, __ldcg(&g_LOGITS[c]));
        __syncthreads();
        red[tid] = lm; __syncthreads();
        for (int o = NTH / 2; o; o >>= 1) {
            if (tid < o) red[tid] = fmaxf(red[tid], red[tid + o]);
            __syncthreads();
        }
        float mx = red[0]; __syncthreads();
        float ls = 0.f;
        for (int c = tid; c < CATS; c += NTH) ls += expf(__ldcg(&g_LOGITS[c]) - mx);
        red[tid] = ls; __syncthreads();
        for (int o = NTH / 2; o; o >>= 1) {
            if (tid < o) red[tid] += red[tid + o];
            __syncthreads();
        }
        float inv = 1.f / red[0];
        for (int c = tid; c < CATS; c += NTH)
            out[c] = expf(__ldcg(&g_LOGITS[c]) - mx) * inv;
    }
}

// ---------------------------------------------------------------------------
extern "C" void kernel_launch(void* const* d_in, const int* in_sizes, int n_in,
                              void* d_out, int out_size)
{
    const float* x       = (const float*)d_in[0];
    const float* Wh      = (const float*)d_in[1];
    const float* Wz      = (const float*)d_in[2];
    // d_in[3] = Wr, d_in[7] = Ur, d_in[8] = br: dead code in reference
    const float* Uh      = (const float*)d_in[4];
    const float* Uz      = (const float*)d_in[5];
    const float* bz      = (const float*)d_in[6];
    const float* Wout    = (const float*)d_in[9];
    // d_in[10] = h0: never read by the reference recurrence
    const float* zt0     = (const float*)d_in[11];
    const float* htilde0 = (const float*)d_in[12];
    const float* hprev0  = (const float*)d_in[13];
    float* out = (float*)d_out;

    dim3 ggrid((NH * 2) / GBN, T_STEPS / GBM);
    gemm_xproj<<<ggrid, 256>>>(x, Wz, Wh);

    cudaFuncSetAttribute(gru_recurrence,
                         cudaFuncAttributeMaxDynamicSharedMemorySize, SMEM_BYTES);
    gru_recurrence<<<NBLK, NTH, SMEM_BYTES>>>(Uz, Uh, bz, Wout,
                                              zt0, htilde0, hprev0, out);
}

// round 12
// speedup vs baseline: 1.6437x; 1.0450x over previous
#include <cuda_runtime.h>
#include <math.h>

// Problem constants
#define T_STEPS 1024
#define D_IN    2048
#define NH      2048
#define CATS    1000

// Recurrence kernel config
#define NBLK    128          // persistent blocks (1 block/SM)
#define NTH     512          // 16 warps
#define HPB     16           // hidden indices owned per block (z AND ht)
#define NSTAGE  26           // rows of U pinned in SMEM per block (of 32)
// smem: U rows + two p buffers (p_t, p_{t+1}) + 128 partials
#define SMEM_FLOATS (NSTAGE*NH + 2*NH + 128)
#define SMEM_BYTES  (SMEM_FLOATS * 4)   // 229888 B

// Scratch (device globals; no allocation allowed)
__device__ float g_XZ[T_STEPS * NH];
__device__ float g_XH[T_STEPS * NH];
__device__ float g_Zb[4][NH];      // gate z, 4-deep ring by generation&3
__device__ float g_HTb[4][NH];     // gate htilde
__device__ float g_LOGITS[1024];
// Barrier state on separate 256B lines (pollers never touch the count line)
__device__ unsigned int g_count[64];
__device__ unsigned int g_gen[64];

// ---------------------------------------------------------------------------
// GEMM v2: C[t, n] = sum_k x[t,k] * W[n,k]; n<2048 -> Wz -> XZ, else Wh->XH.
// 128x128 tile, BK=8, 256 threads, 8x8 microtile (4+4 split), double-buffered
// smem with ONE __syncthreads per K-chunk, 2 blocks/SM.
// ---------------------------------------------------------------------------
#define TBM 128
#define TBN 128
#define TBK 8

__global__ __launch_bounds__(256, 2) void gemm_xproj(
    const float* __restrict__ x,
    const float* __restrict__ Wz,
    const float* __restrict__ Wh)
{
    __shared__ float As[2][TBK][132];   // stride 132 kills k-plane bank collisions
    __shared__ float Bs[2][TBK][132];

    const int tid  = threadIdx.x;
    const int row0 = blockIdx.y * TBM;   // t tile
    const int col0 = blockIdx.x * TBN;   // n tile (uniform half per block)

    const float* Bbase = (col0 < NH) ? (Wz + (size_t)col0 * D_IN)
                                     : (Wh + (size_t)(col0 - NH) * D_IN);

    const int tx = tid & 15;             // m group (8 rows: tx*4+i, 64+tx*4+i)
    const int ty = tid >> 4;             // n group
    const int lr = tid >> 1;             // load row 0..127
    const int lk = (tid & 1) * 4;        // load k offset 0 or 4

    const float* aptr = x + (size_t)(row0 + lr) * D_IN + lk;
    const float* bptr = Bbase + (size_t)lr * D_IN + lk;

    float acc[8][8];
    #pragma unroll
    for (int i = 0; i < 8; i++)
        #pragma unroll
        for (int j = 0; j < 8; j++) acc[i][j] = 0.f;

    // prologue: tile 0
    float4 av = *(const float4*)aptr;
    float4 bv = *(const float4*)bptr;
    As[0][lk + 0][lr] = av.x; As[0][lk + 1][lr] = av.y;
    As[0][lk + 2][lr] = av.z; As[0][lk + 3][lr] = av.w;
    Bs[0][lk + 0][lr] = bv.x; Bs[0][lk + 1][lr] = bv.y;
    Bs[0][lk + 2][lr] = bv.z; Bs[0][lk + 3][lr] = bv.w;
    __syncthreads();

    int cur = 0;
    for (int kt = 0; kt < D_IN; kt += TBK) {
        const bool more = (kt + TBK < D_IN);
        if (more) {
            av = *(const float4*)(aptr + kt + TBK);
            bv = *(const float4*)(bptr + kt + TBK);
        }
        #pragma unroll
        for (int k = 0; k < TBK; k++) {
            float a[8], b[8];
            *(float4*)&a[0] = *(const float4*)&As[cur][k][tx * 4];
            *(float4*)&a[4] = *(const float4*)&As[cur][k][64 + tx * 4];
            *(float4*)&b[0] = *(const float4*)&Bs[cur][k][ty * 4];
            *(float4*)&b[4] = *(const float4*)&Bs[cur][k][64 + ty * 4];
            #pragma unroll
            for (int i = 0; i < 8; i++)
                #pragma unroll
                for (int j = 0; j < 8; j++) acc[i][j] += a[i] * b[j];
        }
        if (more) {
            const int nb = cur ^ 1;
            As[nb][lk + 0][lr] = av.x; As[nb][lk + 1][lr] = av.y;
            As[nb][lk + 2][lr] = av.z; As[nb][lk + 3][lr] = av.w;
            Bs[nb][lk + 0][lr] = bv.x; Bs[nb][lk + 1][lr] = bv.y;
            Bs[nb][lk + 2][lr] = bv.z; Bs[nb][lk + 3][lr] = bv.w;
            __syncthreads();
            cur = nb;
        }
    }

    // epilogue: float4 stores (n quads contiguous)
    #pragma unroll
    for (int i = 0; i < 8; i++) {
        const int t = row0 + ((i < 4) ? (tx * 4 + i) : (64 + tx * 4 + i - 4));
        #pragma unroll
        for (int jh = 0; jh < 2; jh++) {
            const int n = col0 + ((jh == 0) ? (ty * 4) : (64 + ty * 4));
            float4 v = make_float4(acc[i][jh * 4 + 0], acc[i][jh * 4 + 1],
                                   acc[i][jh * 4 + 2], acc[i][jh * 4 + 3]);
            if (n < NH) *(float4*)&g_XZ[(size_t)t * NH + n] = v;
            else        *(float4*)&g_XH[(size_t)t * NH + (n - NH)] = v;
        }
    }
}

// ---------------------------------------------------------------------------
// Barrier arrive+wait with LOCALLY tracked target generation (no gen pre-load
// on the arrive path). acq_rel atomic pulls in all prior releases; last
// arriver resets count then release-stores gen = target; pollers acquire.
// ---------------------------------------------------------------------------
__device__ __forceinline__ void barrier_arrive_wait(unsigned int target)
{
    unsigned int old;
    asm volatile("atom.acq_rel.gpu.global.add.u32 %0, [%1], 1;"
                 : "=r"(old) : "l"(&g_count[0]));
    if (old == NBLK - 1) {
        asm volatile("st.relaxed.gpu.global.u32 [%0], %1;"
                     :: "l"(&g_count[0]), "r"(0u));
        asm volatile("st.release.gpu.global.u32 [%0], %1;"
                     :: "l"(&g_gen[0]), "r"(target));
    } else {
        unsigned int v;
        do {
            asm volatile("ld.acquire.gpu.global.u32 %0, [%1];"
                         : "=r"(v) : "l"(&g_gen[0]));
        } while ((int)(v - target) < 0);
    }
}

// ---------------------------------------------------------------------------
// Persistent recurrence. Block b owns hidden indices [16b,16b+16).
// FUSED superstep: one pass over U computes matvecs for p_t AND p_{t+1}
// (each staged U element read once), producing G(2m+1), G(2m+2). One grid
// barrier per superstep; the gate warp arrives EARLY (only its own STGs need
// ordering -> __syncwarp + release atomic), warps 1-15 overlap the poll.
// ---------------------------------------------------------------------------
__global__ __launch_bounds__(NTH, 1) void gru_recurrence(
    const float* __restrict__ Uz, const float* __restrict__ Uh,
    const float* __restrict__ bz,
    const float* __restrict__ Wout,
    const float* __restrict__ zt0, const float* __restrict__ htilde0,
    const float* __restrict__ hprev0,
    float* __restrict__ out)
{
    extern __shared__ float sm[];
    float* smU  = sm;                    // NSTAGE * NH
    float* psA  = sm + NSTAGE * NH;      // NH : p_t
    float* psB  = psA + NH;              // NH : p_{t+1}
    float* part = psB + NH;              // 128 partials [vec*64 + kh*32 + row]

    const int tid  = threadIdx.x;
    const int w    = tid >> 5;
    const int lane = tid & 31;
    const int wp   = w & 7;              // row group
    const int kh   = w >> 3;             // K half
    const int b    = blockIdx.x;
    const int I0   = b * HPB;

    // Launch-start generation base (stable: no updates until first barrier,
    // and every block reads before its own first arrive).
    unsigned int base = 0;
    if (tid == 0)
        asm volatile("ld.relaxed.gpu.global.u32 %0, [%1];"
                     : "=r"(base) : "l"(&g_gen[0]));

    // Pin NSTAGE matvec rows into SMEM. Row s: s<16 -> Uz[I0+s], else Uh[I0+s-16].
    for (int s = 0; s < NSTAGE; s++) {
        const float* src = (s < 16) ? (Uz + (size_t)(I0 + s) * NH)
                                    : (Uh + (size_t)(I0 + s - 16) * NH);
        for (int i = tid; i < NH / 4; i += NTH)
            ((float4*)(smU + (size_t)s * NH))[i] = ((const float4*)src)[i];
    }

    float4* psA4 = (float4*)psA;
    float4* psB4 = (float4*)psB;

    const float bzv = (tid < 16) ? __ldg(bz + I0 + tid) : 0.f;

    // Per-warp row pointers (K-half slices; float4 index j*32+lane, j<8)
    const int s3 = wp + 24;                       // only it=3 can be residual
    const bool resid = (s3 >= NSTAGE);
    const float4* r0 = (const float4*)(smU + (size_t)(wp)      * NH + kh * 1024);
    const float4* r1 = (const float4*)(smU + (size_t)(wp + 8)  * NH + kh * 1024);
    const float4* r2 = (const float4*)(smU + (size_t)(wp + 16) * NH + kh * 1024);
    const float4* r3 = resid
        ? (const float4*)(Uh + (size_t)(I0 + s3 - 16) * NH + kh * 1024)
        : (const float4*)(smU + (size_t)s3 * NH + kh * 1024);

    __syncthreads();

    // ---- supersteps: 2 timesteps, 1 fused U pass, 1 grid barrier ----
    for (int m = 0; m < T_STEPS / 2; m++) {
        const int t = 2 * m;

        // Prefetch gates for both rolls (G(2m-1), G(2m)) right after barrier.
        float4 zA, hA, zB, hB;
        if (m > 0) {
            const int bA = (t - 1) & 3;
            zA = __ldcg((const float4*)g_Zb[bA]  + tid);
            hA = __ldcg((const float4*)g_HTb[bA] + tid);
            const int bB = t & 3;
            zB = __ldcg((const float4*)g_Zb[bB]  + tid);
            hB = __ldcg((const float4*)g_HTb[bB] + tid);
        } else {
            zB = ((const float4*)zt0)[tid];
            hB = ((const float4*)htilde0)[tid];
        }
        // Residual U row prefetch (constant data; hides L2 latency)
        float4 upre[8];
        if (resid) {
            #pragma unroll
            for (int j = 0; j < 8; j++) upre[j] = __ldg(r3 + j * 32 + lane);
        }
        // x projections for both steps (gate warp only)
        float xv0 = 0.f, xv1 = 0.f;
        if (tid < 32) {
            if (tid < 16) {
                xv0 = __ldg(&g_XZ[(size_t)t * NH + I0 + tid]);
                xv1 = __ldg(&g_XZ[(size_t)(t + 1) * NH + I0 + tid]);
            } else {
                xv0 = __ldg(&g_XH[(size_t)t * NH + I0 + tid - 16]);
                xv1 = __ldg(&g_XH[(size_t)(t + 1) * NH + I0 + tid - 16]);
            }
        }

        // Both rolls, back to back (each thread owns element tid):
        // p_t = roll(p_{t-1}, G(2m-1));  p_{t+1} = roll(p_t, G(2m))
        {
            float4 p = (m == 0) ? ((const float4*)hprev0)[tid] : psB4[tid];
            if (m > 0) {
                p.x = (1.f - zA.x) * p.x + zA.x * hA.x;
                p.y = (1.f - zA.y) * p.y + zA.y * hA.y;
                p.z = (1.f - zA.z) * p.z + zA.z * hA.z;
                p.w = (1.f - zA.w) * p.w + zA.w * hA.w;
            }
            psA4[tid] = p;
            float4 q;
            q.x = (1.f - zB.x) * p.x + zB.x * hB.x;
            q.y = (1.f - zB.y) * p.y + zB.y * hB.y;
            q.z = (1.f - zB.z) * p.z + zB.z * hB.z;
            q.w = (1.f - zB.w) * p.w + zB.w * hB.w;
            psB4[tid] = q;
        }
        __syncthreads();

        // Fused dual matvec: one pass over U, FMA vs p_t AND p_{t+1}
        float aA0 = 0.f, aA1 = 0.f, aA2 = 0.f, aA3 = 0.f;
        float aB0 = 0.f, aB1 = 0.f, aB2 = 0.f, aB3 = 0.f;
        #pragma unroll
        for (int j = 0; j < 8; j++) {
            float4 pA = psA4[kh * 256 + j * 32 + lane];
            float4 pB = psB4[kh * 256 + j * 32 + lane];
            float4 u;
            u = r0[j * 32 + lane];
            aA0 += u.x * pA.x + u.y * pA.y + u.z * pA.z + u.w * pA.w;
            aB0 += u.x * pB.x + u.y * pB.y + u.z * pB.z + u.w * pB.w;
            u = r1[j * 32 + lane];
            aA1 += u.x * pA.x + u.y * pA.y + u.z * pA.z + u.w * pA.w;
            aB1 += u.x * pB.x + u.y * pB.y + u.z * pB.z + u.w * pB.w;
            u = r2[j * 32 + lane];
            aA2 += u.x * pA.x + u.y * pA.y + u.z * pA.z + u.w * pA.w;
            aB2 += u.x * pB.x + u.y * pB.y + u.z * pB.z + u.w * pB.w;
            u = resid ? upre[j] : r3[j * 32 + lane];
            aA3 += u.x * pA.x + u.y * pA.y + u.z * pA.z + u.w * pA.w;
            aB3 += u.x * pB.x + u.y * pB.y + u.z * pB.z + u.w * pB.w;
        }
        #pragma unroll
        for (int off = 16; off; off >>= 1) {
            aA0 += __shfl_xor_sync(0xffffffffu, aA0, off);
            aA1 += __shfl_xor_sync(0xffffffffu, aA1, off);
            aA2 += __shfl_xor_sync(0xffffffffu, aA2, off);
            aA3 += __shfl_xor_sync(0xffffffffu, aA3, off);
            aB0 += __shfl_xor_sync(0xffffffffu, aB0, off);
            aB1 += __shfl_xor_sync(0xffffffffu, aB1, off);
            aB2 += __shfl_xor_sync(0xffffffffu, aB2, off);
            aB3 += __shfl_xor_sync(0xffffffffu, aB3, off);
        }
        if (lane == 0) {
            float* pa = part + kh * 32;        // vec A partials
            pa[wp]      = aA0;
            pa[wp + 8]  = aA1;
            pa[wp + 16] = aA2;
            pa[wp + 24] = aA3;
            float* pb = part + 64 + kh * 32;   // vec B partials
            pb[wp]      = aB0;
            pb[wp + 8]  = aB1;
            pb[wp + 16] = aB2;
            pb[wp + 24] = aB3;
        }
        __syncthreads();

        // Gate warp: both generations, then EARLY barrier arrive.
        // Only warp 0's gate STGs need ordering before the release atomic;
        // __syncwarp() establishes it. Warps 1-15 skip straight to the wait.
        if (tid < 32) {
            float vA = part[tid]      + part[32 + tid];
            float vB = part[64 + tid] + part[96 + tid];
            const int gA = (t + 1) & 3, gB = (t + 2) & 3;
            if (tid < 16) {
                g_Zb[gA][I0 + tid] = 1.f / (1.f + expf(-(xv0 + vA + bzv)));
                g_Zb[gB][I0 + tid] = 1.f / (1.f + expf(-(xv1 + vB + bzv)));
            } else {
                g_HTb[gA][I0 + tid - 16] = tanhf(xv0 + vA);
                g_HTb[gB][I0 + tid - 16] = tanhf(xv1 + vB);
            }
            __syncwarp();
            if (tid == 0) barrier_arrive_wait(base + m + 1);
        }
        __syncthreads();   // all warps held until chip-wide release
    }

    // Final roll: p_1024 = roll(p_1023, G(1023)); result into psA
    {
        const int bF = (T_STEPS - 1) & 3;
        float4 z = __ldcg((const float4*)g_Zb[bF]  + tid);
        float4 h = __ldcg((const float4*)g_HTb[bF] + tid);
        float4 p = psB4[tid];
        p.x = (1.f - z.x) * p.x + z.x * h.x;
        p.y = (1.f - z.y) * p.y + z.y * h.y;
        p.z = (1.f - z.z) * p.z + z.z * h.z;
        p.w = (1.f - z.w) * p.w + z.w * h.w;
        psA4[tid] = p;
    }
    __syncthreads();

    // Logits: warp gw = b*16 + w covers 1000 rows (p from local smem)
    {
        int gw = b * 16 + w;
        if (gw < CATS) {
            const float4* u4 = (const float4*)(Wout + (size_t)gw * NH);
            float acc = 0.f;
            #pragma unroll
            for (int j = 0; j < 16; j++) {
                float4 u = __ldg(u4 + j * 32 + lane);
                float4 p = psA4[j * 32 + lane];
                acc += u.x * p.x + u.y * p.y + u.z * p.z + u.w * p.w;
            }
            #pragma unroll
            for (int off = 16; off; off >>= 1)
                acc += __shfl_xor_sync(0xffffffffu, acc, off);
            if (lane == 0) g_LOGITS[gw] = acc;
        }
    }
    // Logit STGs come from all warps -> full block sync before arrive.
    __syncthreads();
    if (tid == 0) barrier_arrive_wait(base + T_STEPS / 2 + 1);
    __syncthreads();

    // Softmax in block 0 (reduction buffer reuses psB)
    if (b == 0) {
        float* red = psB;
        float lm = -1e30f;
        for (int c = tid; c < CATS; c += NTH) lm = fmaxf(lm, __ldcg(&g_LOGITS[c]));
        __syncthreads();
        red[tid] = lm; __syncthreads();
        for (int o = NTH / 2; o; o >>= 1) {
            if (tid < o) red[tid] = fmaxf(red[tid], red[tid + o]);
            __syncthreads();
        }
        float mx = red[0]; __syncthreads();
        float ls = 0.f;
        for (int c = tid; c < CATS; c += NTH) ls += expf(__ldcg(&g_LOGITS[c]) - mx);
        red[tid] = ls; __syncthreads();
        for (int o = NTH / 2; o; o >>= 1) {
            if (tid < o) red[tid] += red[tid + o];
            __syncthreads();
        }
        float inv = 1.f / red[0];
        for (int c = tid; c < CATS; c += NTH)
            out[c] = expf(__ldcg(&g_LOGITS[c]) - mx) * inv;
    }
}

// ---------------------------------------------------------------------------
extern "C" void kernel_launch(void* const* d_in, const int* in_sizes, int n_in,
                              void* d_out, int out_size)
{
    const float* x       = (const float*)d_in[0];
    const float* Wh      = (const float*)d_in[1];
    const float* Wz      = (const float*)d_in[2];
    // d_in[3] = Wr, d_in[7] = Ur, d_in[8] = br: dead code in reference
    const float* Uh      = (const float*)d_in[4];
    const float* Uz      = (const float*)d_in[5];
    const float* bz      = (const float*)d_in[6];
    const float* Wout    = (const float*)d_in[9];
    // d_in[10] = h0: never read by the reference recurrence
    const float* zt0     = (const float*)d_in[11];
    const float* htilde0 = (const float*)d_in[12];
    const float* hprev0  = (const float*)d_in[13];
    float* out = (float*)d_out;

    dim3 ggrid((NH * 2) / TBN, T_STEPS / TBM);   // (32, 8)
    gemm_xproj<<<ggrid, 256>>>(x, Wz, Wh);

    cudaFuncSetAttribute(gru_recurrence,
                         cudaFuncAttributeMaxDynamicSharedMemorySize, SMEM_BYTES);
    gru_recurrence<<<NBLK, NTH, SMEM_BYTES>>>(Uz, Uh, bz, Wout,
                                              zt0, htilde0, hprev0, out);
}

// round 15
// speedup vs baseline: 1.6620x; 1.0111x over previous
#include <cuda_runtime.h>
#include <math.h>

// Problem constants
#define T_STEPS 1024
#define D_IN    2048
#define NH      2048
#define CATS    1000

// Recurrence kernel config
#define NBLK    128          // persistent blocks (1 block/SM)
#define NTH     512          // 16 warps
#define HPB     16           // hidden indices owned per block (z AND ht)
#define NSTAGE  26           // rows of U pinned in SMEM per block (of 32)
// smem: U rows + two p buffers (p_t, p_{t+1}) + 128 partials
#define SMEM_FLOATS (NSTAGE*NH + 2*NH + 128)
#define SMEM_BYTES  (SMEM_FLOATS * 4)   // 229888 B

// Scratch (device globals; no allocation allowed)
__device__ float g_XZ[T_STEPS * NH];
__device__ float g_XH[T_STEPS * NH];
__device__ float g_Pb[4][NH];      // p ring by generation&3 (ONLY exchange)
__device__ float g_LOGITS[1024];
// Barrier state on separate 256B lines (pollers never touch the count line)
__device__ unsigned int g_count[64];
__device__ unsigned int g_gen[64];

// ---------------------------------------------------------------------------
// GEMM v2 (round-12 proven): 128x128 tile, BK=8, 256 thr, 8x8 microtile,
// double-buffered smem, one __syncthreads per K-chunk, 2 blocks/SM.
// ---------------------------------------------------------------------------
#define TBM 128
#define TBN 128
#define TBK 8

__global__ __launch_bounds__(256, 2) void gemm_xproj(
    const float* __restrict__ x,
    const float* __restrict__ Wz,
    const float* __restrict__ Wh)
{
    __shared__ float As[2][TBK][132];
    __shared__ float Bs[2][TBK][132];

    const int tid  = threadIdx.x;
    const int row0 = blockIdx.y * TBM;
    const int col0 = blockIdx.x * TBN;

    const float* Bbase = (col0 < NH) ? (Wz + (size_t)col0 * D_IN)
                                     : (Wh + (size_t)(col0 - NH) * D_IN);

    const int tx = tid & 15;
    const int ty = tid >> 4;
    const int lr = tid >> 1;
    const int lk = (tid & 1) * 4;

    const float* aptr = x + (size_t)(row0 + lr) * D_IN + lk;
    const float* bptr = Bbase + (size_t)lr * D_IN + lk;

    float acc[8][8];
    #pragma unroll
    for (int i = 0; i < 8; i++)
        #pragma unroll
        for (int j = 0; j < 8; j++) acc[i][j] = 0.f;

    float4 av = *(const float4*)aptr;
    float4 bv = *(const float4*)bptr;
    As[0][lk + 0][lr] = av.x; As[0][lk + 1][lr] = av.y;
    As[0][lk + 2][lr] = av.z; As[0][lk + 3][lr] = av.w;
    Bs[0][lk + 0][lr] = bv.x; Bs[0][lk + 1][lr] = bv.y;
    Bs[0][lk + 2][lr] = bv.z; Bs[0][lk + 3][lr] = bv.w;
    __syncthreads();

    int cur = 0;
    for (int kt = 0; kt < D_IN; kt += TBK) {
        const bool more = (kt + TBK < D_IN);
        if (more) {
            av = *(const float4*)(aptr + kt + TBK);
            bv = *(const float4*)(bptr + kt + TBK);
        }
        #pragma unroll
        for (int k = 0; k < TBK; k++) {
            float a[8], b[8];
            *(float4*)&a[0] = *(const float4*)&As[cur][k][tx * 4];
            *(float4*)&a[4] = *(const float4*)&As[cur][k][64 + tx * 4];
            *(float4*)&b[0] = *(const float4*)&Bs[cur][k][ty * 4];
            *(float4*)&b[4] = *(const float4*)&Bs[cur][k][64 + ty * 4];
            #pragma unroll
            for (int i = 0; i < 8; i++)
                #pragma unroll
                for (int j = 0; j < 8; j++) acc[i][j] += a[i] * b[j];
        }
        if (more) {
            const int nb = cur ^ 1;
            As[nb][lk + 0][lr] = av.x; As[nb][lk + 1][lr] = av.y;
            As[nb][lk + 2][lr] = av.z; As[nb][lk + 3][lr] = av.w;
            Bs[nb][lk + 0][lr] = bv.x; Bs[nb][lk + 1][lr] = bv.y;
            Bs[nb][lk + 2][lr] = bv.z; Bs[nb][lk + 3][lr] = bv.w;
            __syncthreads();
            cur = nb;
        }
    }

    #pragma unroll
    for (int i = 0; i < 8; i++) {
        const int t = row0 + ((i < 4) ? (tx * 4 + i) : (64 + tx * 4 + i - 4));
        #pragma unroll
        for (int jh = 0; jh < 2; jh++) {
            const int n = col0 + ((jh == 0) ? (ty * 4) : (64 + ty * 4));
            float4 v = make_float4(acc[i][jh * 4 + 0], acc[i][jh * 4 + 1],
                                   acc[i][jh * 4 + 2], acc[i][jh * 4 + 3]);
            if (n < NH) *(float4*)&g_XZ[(size_t)t * NH + n] = v;
            else        *(float4*)&g_XH[(size_t)t * NH + (n - NH)] = v;
        }
    }
}

// ---------------------------------------------------------------------------
// Barrier arrive+wait with locally tracked target generation.
// ---------------------------------------------------------------------------
__device__ __forceinline__ void barrier_arrive_wait(unsigned int target)
{
    unsigned int old;
    asm volatile("atom.acq_rel.gpu.global.add.u32 %0, [%1], 1;"
                 : "=r"(old) : "l"(&g_count[0]));
    if (old == NBLK - 1) {
        asm volatile("st.relaxed.gpu.global.u32 [%0], %1;"
                     :: "l"(&g_count[0]), "r"(0u));
        asm volatile("st.release.gpu.global.u32 [%0], %1;"
                     :: "l"(&g_gen[0]), "r"(target));
    } else {
        unsigned int v;
        do {
            asm volatile("ld.acquire.gpu.global.u32 %0, [%1];"
                         : "=r"(v) : "l"(&g_gen[0]));
        } while ((int)(v - target) < 0);
    }
}

// ---------------------------------------------------------------------------
// Persistent recurrence, p-ring exchange. Block b owns indices [16b,16b+16).
// Superstep m (t=2m): stage p_t, p_{t+1} from the ring; one fused U pass
// gives own-row gates for gens t+1, t+2; LOCAL 16-element rolls produce
// p_{t+2}, p_{t+3}[own] which are published (128B). Gates never leave the
// block. Gate math + rolls are distributed over warps 0-7 (lane r<8: one
// gate value each; lanes 0-1 do the rolls via intra-warp shuffles).
// ---------------------------------------------------------------------------
__global__ __launch_bounds__(NTH, 1) void gru_recurrence(
    const float* __restrict__ Uz, const float* __restrict__ Uh,
    const float* __restrict__ bz,
    const float* __restrict__ Wout,
    const float* __restrict__ zt0, const float* __restrict__ htilde0,
    const float* __restrict__ hprev0,
    float* __restrict__ out)
{
    extern __shared__ float sm[];
    float* smU  = sm;                    // NSTAGE * NH
    float* psA  = sm + NSTAGE * NH;      // NH : p_t stage
    float* psB  = psA + NH;              // NH : p_{t+1} stage
    float* part = psB + NH;              // 128 partials [w*8 + (vec*4+it)]

    const int tid  = threadIdx.x;
    const int w    = tid >> 5;
    const int lane = tid & 31;
    const int wp   = w & 7;              // row group
    const int kh   = w >> 3;             // K half
    const int b    = blockIdx.x;
    const int I0   = b * HPB;

    unsigned int base = 0;
    if (tid == 0)
        asm volatile("ld.relaxed.gpu.global.u32 %0, [%1];"
                     : "=r"(base) : "l"(&g_gen[0]));

    // Pin NSTAGE matvec rows into SMEM. Row s: s<16 -> Uz[I0+s], else Uh[I0+s-16].
    for (int s = 0; s < NSTAGE; s++) {
        const float* src = (s < 16) ? (Uz + (size_t)(I0 + s) * NH)
                                    : (Uh + (size_t)(I0 + s - 16) * NH);
        for (int i = tid; i < NH / 4; i += NTH)
            ((float4*)(smU + (size_t)s * NH))[i] = ((const float4*)src)[i];
    }

    float4* psA4 = (float4*)psA;
    float4* psB4 = (float4*)psB;

    // Gate-lane constants (warps 0-7, lanes 0-7): r = vec*4+it
    const bool gate_lane = (w < 8) && (lane < 8);
    const int g_vec = lane >> 2;         // 0: gen from p_t, 1: from p_{t+1}
    const int g_it  = lane & 3;          // row s = wp + 8*it
    const int g_i   = I0 + wp + 8 * (g_it & 1);   // hidden index of this gate
    const bool g_isz = (g_it < 2);
    const float bzv = gate_lane && g_isz ? __ldg(bz + g_i) : 0.f;

    // Per-warp row pointers (K-half slices; float4 index j*32+lane, j<8)
    const int s3 = wp + 24;                       // only it=3 can be residual
    const bool resid = (s3 >= NSTAGE);
    const float4* r0 = (const float4*)(smU + (size_t)(wp)      * NH + kh * 1024);
    const float4* r1 = (const float4*)(smU + (size_t)(wp + 8)  * NH + kh * 1024);
    const float4* r2 = (const float4*)(smU + (size_t)(wp + 16) * NH + kh * 1024);
    const float4* r3 = resid
        ? (const float4*)(Uh + (size_t)(I0 + s3 - 16) * NH + kh * 1024)
        : (const float4*)(smU + (size_t)s3 * NH + kh * 1024);

    // Prologue: publish p_0, p_1 for own indices; barrier.
    if (tid < 16) {
        int i = I0 + tid;
        float p0 = hprev0[i];
        float z  = zt0[i], h = htilde0[i];
        g_Pb[0][i] = p0;
        g_Pb[1][i] = (1.f - z) * p0 + z * h;
    }
    __syncthreads();
    if (tid == 0) barrier_arrive_wait(base + 1);
    __syncthreads();

    // ---- supersteps: 2 timesteps, 1 fused U pass, 1 grid barrier ----
    for (int m = 0; m < T_STEPS / 2; m++) {
        const int t = 2 * m;

        // Gate-lane x projection for this superstep (overlaps staging)
        float xvv = 0.f;
        if (gate_lane) {
            xvv = g_isz ? __ldg(&g_XZ[(size_t)(t + g_vec) * NH + g_i])
                        : __ldg(&g_XH[(size_t)(t + g_vec) * NH + g_i]);
        }
        // Residual U row prefetch (constant data; hides L2 latency)
        float4 upre[8];
        if (resid) {
            #pragma unroll
            for (int j = 0; j < 8; j++) upre[j] = __ldg(r3 + j * 32 + lane);
        }

        // Stage p_t, p_{t+1} from the ring (bypass L1)
        psA4[tid] = __ldcg((const float4*)g_Pb[t & 3] + tid);
        psB4[tid] = __ldcg((const float4*)g_Pb[(t + 1) & 3] + tid);
        __syncthreads();

        // Fused dual matvec: one pass over U, FMA vs p_t AND p_{t+1}
        float aA0 = 0.f, aA1 = 0.f, aA2 = 0.f, aA3 = 0.f;
        float aB0 = 0.f, aB1 = 0.f, aB2 = 0.f, aB3 = 0.f;
        #pragma unroll
        for (int j = 0; j < 8; j++) {
            float4 pA = psA4[kh * 256 + j * 32 + lane];
            float4 pB = psB4[kh * 256 + j * 32 + lane];
            float4 u;
            u = r0[j * 32 + lane];
            aA0 += u.x * pA.x + u.y * pA.y + u.z * pA.z + u.w * pA.w;
            aB0 += u.x * pB.x + u.y * pB.y + u.z * pB.z + u.w * pB.w;
            u = r1[j * 32 + lane];
            aA1 += u.x * pA.x + u.y * pA.y + u.z * pA.z + u.w * pA.w;
            aB1 += u.x * pB.x + u.y * pB.y + u.z * pB.z + u.w * pB.w;
            u = r2[j * 32 + lane];
            aA2 += u.x * pA.x + u.y * pA.y + u.z * pA.z + u.w * pA.w;
            aB2 += u.x * pB.x + u.y * pB.y + u.z * pB.z + u.w * pB.w;
            u = resid ? upre[j] : r3[j * 32 + lane];
            aA3 += u.x * pA.x + u.y * pA.y + u.z * pA.z + u.w * pA.w;
            aB3 += u.x * pB.x + u.y * pB.y + u.z * pB.z + u.w * pB.w;
        }
        #pragma unroll
        for (int off = 16; off; off >>= 1) {
            aA0 += __shfl_xor_sync(0xffffffffu, aA0, off);
            aA1 += __shfl_xor_sync(0xffffffffu, aA1, off);
            aA2 += __shfl_xor_sync(0xffffffffu, aA2, off);
            aA3 += __shfl_xor_sync(0xffffffffu, aA3, off);
            aB0 += __shfl_xor_sync(0xffffffffu, aB0, off);
            aB1 += __shfl_xor_sync(0xffffffffu, aB1, off);
            aB2 += __shfl_xor_sync(0xffffffffu, aB2, off);
            aB3 += __shfl_xor_sync(0xffffffffu, aB3, off);
        }
        if (lane == 0) {
            float* pt = part + w * 8;
            pt[0] = aA0; pt[1] = aA1; pt[2] = aA2; pt[3] = aA3;
            pt[4] = aB0; pt[5] = aB1; pt[6] = aB2; pt[7] = aB3;
        }
        __syncthreads();

        // Warps 0-7: combine K-halves, compute gates (1/lane), local rolls,
        // publish own p_{t+2}, p_{t+3}; then named-barrier + early arrive.
        if (w < 8) {
            if (lane < 8) {
                float v = part[w * 8 + lane] + part[(w + 8) * 8 + lane];
                float g;
                if (g_isz) g = 1.f / (1.f + expf(-(xvv + v + bzv)));
                else       g = tanhf(xvv + v);
                // Gather this index-pair's 4 gate values (L = lane&1 selects
                // index wp+8L): z1@r=L, ht1@r=2+L, z2@r=4+L, ht2@r=6+L.
                const int L = lane & 1;
                float z1 = __shfl_sync(0xFFu, g, L);
                float h1 = __shfl_sync(0xFFu, g, 2 + L);
                float z2 = __shfl_sync(0xFFu, g, 4 + L);
                float h2 = __shfl_sync(0xFFu, g, 6 + L);
                if (lane < 2) {
                    const int i = I0 + wp + 8 * L;
                    float p1 = psB[i];
                    float p2 = (1.f - z1) * p1 + z1 * h1;
                    float p3 = (1.f - z2) * p2 + z2 * h2;
                    g_Pb[(t + 2) & 3][i] = p2;
                    g_Pb[(t + 3) & 3][i] = p3;
                }
            }
            // Named barrier over warps 0-7 orders their STGs, then arrive.
            asm volatile("bar.sync 1, 256;" ::: "memory");
            if (tid == 0) barrier_arrive_wait(base + m + 2);
        }
        __syncthreads();   // all warps held until chip-wide release
    }

    // p_1024 is in ring slot 0 (1024 & 3). Stage for logits.
    psA4[tid] = __ldcg((const float4*)g_Pb[0] + tid);
    __syncthreads();

    // Logits: warp gw = b*16 + w covers 1000 rows
    {
        int gw = b * 16 + w;
        if (gw < CATS) {
            const float4* u4 = (const float4*)(Wout + (size_t)gw * NH);
            float acc = 0.f;
            #pragma unroll
            for (int j = 0; j < 16; j++) {
                float4 u = __ldg(u4 + j * 32 + lane);
                float4 p = psA4[j * 32 + lane];
                acc += u.x * p.x + u.y * p.y + u.z * p.z + u.w * p.w;
            }
            #pragma unroll
            for (int off = 16; off; off >>= 1)
                acc += __shfl_xor_sync(0xffffffffu, acc, off);
            if (lane == 0) g_LOGITS[gw] = acc;
        }
    }
    __syncthreads();
    if (tid == 0) barrier_arrive_wait(base + T_STEPS / 2 + 2);
    __syncthreads();

    // Softmax in block 0 (reduction buffer reuses psB)
    if (b == 0) {
        float* red = psB;
        float lm = -1e30f;
        for (int c = tid; c < CATS; c += NTH) lm = fmaxf(lm, __ldcg(&g_LOGITS[c]));
        __syncthreads();
        red[tid] = lm; __syncthreads();
        for (int o = NTH / 2; o; o >>= 1) {
            if (tid < o) red[tid] = fmaxf(red[tid], red[tid + o]);
            __syncthreads();
        }
        float mx = red[0]; __syncthreads();
        float ls = 0.f;
        for (int c = tid; c < CATS; c += NTH) ls += expf(__ldcg(&g_LOGITS[c]) - mx);
        red[tid] = ls; __syncthreads();
        for (int o = NTH / 2; o; o >>= 1) {
            if (tid < o) red[tid] += red[tid + o];
            __syncthreads();
        }
        float inv = 1.f / red[0];
        for (int c = tid; c < CATS; c += NTH)
            out[c] = expf(__ldcg(&g_LOGITS[c]) - mx) * inv;
    }
}

// ---------------------------------------------------------------------------
extern "C" void kernel_launch(void* const* d_in, const int* in_sizes, int n_in,
                              void* d_out, int out_size)
{
    const float* x       = (const float*)d_in[0];
    const float* Wh      = (const float*)d_in[1];
    const float* Wz      = (const float*)d_in[2];
    // d_in[3] = Wr, d_in[7] = Ur, d_in[8] = br: dead code in reference
    const float* Uh      = (const float*)d_in[4];
    const float* Uz      = (const float*)d_in[5];
    const float* bz      = (const float*)d_in[6];
    const float* Wout    = (const float*)d_in[9];
    // d_in[10] = h0: never read by the reference recurrence
    const float* zt0     = (const float*)d_in[11];
    const float* htilde0 = (const float*)d_in[12];
    const float* hprev0  = (const float*)d_in[13];
    float* out = (float*)d_out;

    dim3 ggrid((NH * 2) / TBN, T_STEPS / TBM);   // (32, 8)
    gemm_xproj<<<ggrid, 256>>>(x, Wz, Wh);

    cudaFuncSetAttribute(gru_recurrence,
                         cudaFuncAttributeMaxDynamicSharedMemorySize, SMEM_BYTES);
    gru_recurrence<<<NBLK, NTH, SMEM_BYTES>>>(Uz, Uh, bz, Wout,
                                              zt0, htilde0, hprev0, out);
}